// round 2
// baseline (speedup 1.0000x reference)
#include <cuda_runtime.h>
#include <cstdint>

#define HN   128
#define MAXN 100000
#define MAXE 1600000
#define MAXS 10000

// ---------------- scratch (static device globals; no allocation) ----------------
__device__ float g_bufA[(size_t)MAXN * HN];   // 51.2 MB
__device__ float g_bufB[(size_t)MAXN * HN];   // 51.2 MB
__device__ float g_aggH[(size_t)MAXN * HN];   // 51.2 MB
__device__ float g_agg0[MAXN];
__device__ float g_pool[(size_t)MAXS * HN];   // 5.1 MB
__device__ int   g_ei[2 * MAXE];              // 12.8 MB (src | dst)
__device__ int   g_sub[MAXN];
__device__ int   g_s2g[MAXS];
__device__ int   g_is64;

// ---------------- index dtype detection + normalization ----------------
// If the data is int64 (values in [0, 2^31)), every 8-byte word has a zero high
// half. If it is int32, the "high half" is the next index value; 64 consecutive
// zero index values never happens with random indices in [0, 100000).
__global__ void k_detect(const unsigned long long* __restrict__ p) {
    if (blockIdx.x == 0 && threadIdx.x == 0) {
        int is64 = 1;
        for (int i = 0; i < 64; i++) {
            if (p[i] >> 32) { is64 = 0; break; }
        }
        g_is64 = is64;
    }
}

__global__ void k_convert(const void* __restrict__ in, int* __restrict__ out, int n) {
    int i = blockIdx.x * blockDim.x + threadIdx.x;
    if (i >= n) return;
    if (g_is64) out[i] = (int)(((const long long*)in)[i]);
    else        out[i] = ((const int*)in)[i];
}

// ---------------- utility ----------------
__global__ void k_zero4(float* __restrict__ p, int n4) {
    int i = blockIdx.x * blockDim.x + threadIdx.x;
    if (i < n4) ((float4*)p)[i] = make_float4(0.f, 0.f, 0.f, 0.f);
}

// ---------------- layer 1: scalar aggregation + expansion ----------------
__global__ void k_edge_scalar(const int* __restrict__ src, const int* __restrict__ dst,
                              const float* __restrict__ x, float* __restrict__ agg, int E) {
    int e = blockIdx.x * blockDim.x + threadIdx.x;
    if (e < E) atomicAdd(agg + dst[e], x[src[e]]);
}

__global__ void k_fc1(const float* __restrict__ x, const float* __restrict__ agg0,
                      const float* __restrict__ W1, const float* __restrict__ b1,
                      float* __restrict__ out, int n) {
    int idx = blockIdx.x * blockDim.x + threadIdx.x;
    if (idx >= n * HN) return;
    int node = idx >> 7;
    int j    = idx & (HN - 1);
    float v = fmaf(x[node] + agg0[node], W1[j], b1[j]);
    out[idx] = fmaxf(v, 0.f);
}

// ---------------- feature aggregation: one warp per edge ----------------
__global__ __launch_bounds__(256) void k_edge_vec(
    const int* __restrict__ src, const int* __restrict__ dst,
    const float* __restrict__ hin, float* __restrict__ agg, int E) {
    int gid  = blockIdx.x * blockDim.x + threadIdx.x;
    int e    = gid >> 5;
    int lane = threadIdx.x & 31;
    if (e >= E) return;
    int s = src[e], d = dst[e];
    float4 v = __ldg(((const float4*)(hin + (size_t)s * HN)) + lane);
    float* base = agg + (size_t)d * HN + lane * 4;
    atomicAdd(base + 0, v.x);
    atomicAdd(base + 1, v.y);
    atomicAdd(base + 2, v.z);
    atomicAdd(base + 3, v.w);
}

// ---------------- fused (A [+Agg]) @ W + b, relu ----------------
// Block: 256 threads, tile 64 rows x 128 cols. Each thread: 8 rows x 4 cols.
// W (64KB) + A tile (32KB) in dynamic smem.
extern __shared__ float s_mem[];
__global__ __launch_bounds__(256) void k_gemm_relu(
    const float* __restrict__ A, const float* __restrict__ Agg,
    const float* __restrict__ W, const float* __restrict__ bias,
    float* __restrict__ Out, int nrows, int addAgg) {
    const int TM = 64;
    float* sW = s_mem;            // HN*HN floats
    float* sA = s_mem + HN * HN;  // TM*HN floats

    int tid  = threadIdx.x;
    int row0 = blockIdx.x * TM;

    // load W (full 128x128)
    for (int i = tid; i < HN * HN / 4; i += 256)
        ((float4*)sW)[i] = ((const float4*)W)[i];

    // load A tile (optionally + Agg)
    int tr = nrows - row0; if (tr > TM) tr = TM;
    for (int i = tid; i < TM * HN / 4; i += 256) {
        int elem = i * 4;
        int r = elem >> 7;
        float4 v = make_float4(0.f, 0.f, 0.f, 0.f);
        if (r < tr) {
            size_t off = (size_t)(row0 + r) * HN + (elem & (HN - 1));
            v = *(const float4*)(A + off);
            if (addAgg) {
                float4 g = *(const float4*)(Agg + off);
                v.x += g.x; v.y += g.y; v.z += g.z; v.w += g.w;
            }
        }
        ((float4*)sA)[i] = v;
    }
    __syncthreads();

    int cx = tid & 31;   // column group: cols 4*cx .. 4*cx+3
    int ry = tid >> 5;   // row group: rows ry*8 .. ry*8+7 (warp-uniform)

    float acc[8][4];
#pragma unroll
    for (int r = 0; r < 8; r++)
#pragma unroll
        for (int c = 0; c < 4; c++) acc[r][c] = 0.f;

    const float* sArow = sA + (size_t)(ry * 8) * HN;
#pragma unroll 4
    for (int k = 0; k < HN; k++) {
        float4 w = ((const float4*)(sW + (size_t)k * HN))[cx];
#pragma unroll
        for (int r = 0; r < 8; r++) {
            float a = sArow[r * HN + k];   // warp-broadcast LDS
            acc[r][0] = fmaf(a, w.x, acc[r][0]);
            acc[r][1] = fmaf(a, w.y, acc[r][1]);
            acc[r][2] = fmaf(a, w.z, acc[r][2]);
            acc[r][3] = fmaf(a, w.w, acc[r][3]);
        }
    }

    float4 b = ((const float4*)bias)[cx];
#pragma unroll
    for (int r = 0; r < 8; r++) {
        int row = row0 + ry * 8 + r;
        if (row < nrows) {
            float4 o;
            o.x = fmaxf(acc[r][0] + b.x, 0.f);
            o.y = fmaxf(acc[r][1] + b.y, 0.f);
            o.z = fmaxf(acc[r][2] + b.z, 0.f);
            o.w = fmaxf(acc[r][3] + b.w, 0.f);
            ((float4*)(Out + (size_t)row * HN))[cx] = o;
        }
    }
}

// ---------------- pooling ----------------
__global__ void k_pool1(const float* __restrict__ h, const int* __restrict__ sub,
                        float* __restrict__ pool, int n) {
    int idx = blockIdx.x * blockDim.x + threadIdx.x;
    if (idx >= n * HN) return;
    int node = idx >> 7;
    int j    = idx & (HN - 1);
    atomicAdd(&pool[(size_t)sub[node] * HN + j], h[idx]);
}

__global__ void k_pool2(const float* __restrict__ pool, const int* __restrict__ s2g,
                        float* __restrict__ out, int s_count) {
    int idx = blockIdx.x * blockDim.x + threadIdx.x;
    if (idx >= s_count * HN) return;
    int s = idx >> 7;
    int j = idx & (HN - 1);
    atomicAdd(&out[(size_t)s2g[s] * HN + j], pool[idx]);
}

// ---------------- launch ----------------
extern "C" void kernel_launch(void* const* d_in, const int* in_sizes, int n_in,
                              void* d_out, int out_size) {
    const float* x     = (const float*)d_in[0];
    const void*  ei    = d_in[1];
    const void*  n2s   = d_in[2];
    const void*  s2g_i = d_in[3];
    const float* c1W1  = (const float*)d_in[4];
    const float* c1b1  = (const float*)d_in[5];
    const float* c1W2  = (const float*)d_in[6];
    const float* c1b2  = (const float*)d_in[7];
    const float* cW1   = (const float*)d_in[8];
    const float* cb1   = (const float*)d_in[9];
    const float* cW2   = (const float*)d_in[10];
    const float* cb2   = (const float*)d_in[11];

    int N = in_sizes[0];
    int E = in_sizes[1] / 2;
    int S = in_sizes[3];
    int G = out_size / HN;

    float *bufA, *bufB, *aggH, *agg0, *pool;
    int *eiX, *sub, *s2gX;
    cudaGetSymbolAddress((void**)&bufA, g_bufA);
    cudaGetSymbolAddress((void**)&bufB, g_bufB);
    cudaGetSymbolAddress((void**)&aggH, g_aggH);
    cudaGetSymbolAddress((void**)&agg0, g_agg0);
    cudaGetSymbolAddress((void**)&pool, g_pool);
    cudaGetSymbolAddress((void**)&eiX,  g_ei);
    cudaGetSymbolAddress((void**)&sub,  g_sub);
    cudaGetSymbolAddress((void**)&s2gX, g_s2g);

    const int SMEM = (HN * HN + 64 * HN) * (int)sizeof(float);  // 96 KB
    cudaFuncSetAttribute(k_gemm_relu, cudaFuncAttributeMaxDynamicSharedMemorySize, SMEM);

    // normalize index dtypes
    k_detect<<<1, 1>>>((const unsigned long long*)ei);
    k_convert<<<(2 * E + 255) / 256, 256>>>(ei, eiX, 2 * E);
    k_convert<<<(N + 255) / 256, 256>>>(n2s, sub, N);
    k_convert<<<(S + 255) / 256, 256>>>(s2g_i, s2gX, S);

    // layer 1 (scalar features)
    k_zero4<<<(N / 4 + 255) / 256, 256>>>(agg0, N / 4);
    k_edge_scalar<<<(E + 255) / 256, 256>>>(eiX, eiX + E, x, agg0, E);
    k_fc1<<<((size_t)N * HN + 255) / 256, 256>>>(x, agg0, c1W1, c1b1, bufA, N);

    int gblocks = (N + 63) / 64;
    k_gemm_relu<<<gblocks, 256, SMEM>>>(bufA, nullptr, c1W2, c1b2, bufB, N, 0);

    // layers 2..3
    int nh4 = (int)((size_t)N * HN / 4);
    for (int i = 0; i < 2; i++) {
        k_zero4<<<(nh4 + 255) / 256, 256>>>(aggH, nh4);
        k_edge_vec<<<((size_t)E * 32 + 255) / 256, 256>>>(eiX, eiX + E, bufB, aggH, E);
        k_gemm_relu<<<gblocks, 256, SMEM>>>(bufB, aggH, cW1 + (size_t)i * HN * HN,
                                            cb1 + (size_t)i * HN, bufA, N, 1);
        k_gemm_relu<<<gblocks, 256, SMEM>>>(bufA, nullptr, cW2 + (size_t)i * HN * HN,
                                            cb2 + (size_t)i * HN, bufB, N, 0);
    }

    // pooling: nodes -> subgraphs -> graphs
    k_zero4<<<((S * HN / 4) + 255) / 256, 256>>>(pool, S * HN / 4);
    k_zero4<<<((G * HN / 4) + 255) / 256, 256>>>((float*)d_out, G * HN / 4);
    k_pool1<<<((size_t)N * HN + 255) / 256, 256>>>(bufB, sub, pool, N);
    k_pool2<<<((size_t)S * HN + 255) / 256, 256>>>(pool, s2gX, (float*)d_out, S);
}

// round 3
// speedup vs baseline: 1.6932x; 1.6932x over previous
#include <cuda_runtime.h>
#include <cstdint>

#define HN   128
#define MAXN 100000
#define MAXE 1600000
#define MAXS 10000
#define TM   64

// ---------------- scratch (static device globals; no allocation) ----------------
__device__ float g_bufA[(size_t)MAXN * HN];   // 51.2 MB
__device__ float g_bufB[(size_t)MAXN * HN];   // 51.2 MB
__device__ float g_agg0[MAXN];
__device__ float g_pool[(size_t)MAXS * HN];
__device__ int   g_ei[2 * MAXE];              // src | dst (int32-normalized)
__device__ int   g_sub[MAXN];
__device__ int   g_s2g[MAXS];
__device__ int   g_deg[MAXN];
__device__ int   g_offs[MAXN + 1];
__device__ int   g_cursor[MAXN];
__device__ int   g_csr[MAXE];
__device__ int   g_is64;

// ---------------- index dtype detection + normalization ----------------
__global__ void k_detect(const unsigned long long* __restrict__ p) {
    if (blockIdx.x == 0 && threadIdx.x == 0) {
        int is64 = 1;
        for (int i = 0; i < 64; i++)
            if (p[i] >> 32) { is64 = 0; break; }
        g_is64 = is64;
    }
}

__global__ void k_convert(const void* __restrict__ in, int* __restrict__ out, int n) {
    int i = blockIdx.x * blockDim.x + threadIdx.x;
    if (i >= n) return;
    if (g_is64) out[i] = (int)(((const long long*)in)[i]);
    else        out[i] = ((const int*)in)[i];
}

// ---------------- utility ----------------
__global__ void k_zero4(float* __restrict__ p, int n4) {
    int i = blockIdx.x * blockDim.x + threadIdx.x;
    if (i < n4) ((float4*)p)[i] = make_float4(0.f, 0.f, 0.f, 0.f);
}
__global__ void k_zeroi(int* __restrict__ p, int n) {
    int i = blockIdx.x * blockDim.x + threadIdx.x;
    if (i < n) p[i] = 0;
}

// ---------------- CSR build ----------------
__global__ void k_hist(const int* __restrict__ dst, int* __restrict__ deg, int E) {
    int e = blockIdx.x * blockDim.x + threadIdx.x;
    if (e < E) atomicAdd(deg + dst[e], 1);
}

// single-block exclusive scan over deg[0..n) -> offs[0..n]
__global__ void k_scan(const int* __restrict__ deg, int* __restrict__ offs, int n) {
    __shared__ int sums[1024];
    int tid = threadIdx.x;
    int chunk = (n + 1023) / 1024;
    int start = tid * chunk;
    int end   = start + chunk; if (end > n) end = n;
    int s = 0;
    for (int i = start; i < end; i++) s += deg[i];
    sums[tid] = s;
    __syncthreads();
    for (int off = 1; off < 1024; off <<= 1) {
        int v = 0;
        if (tid >= off) v = sums[tid - off];
        __syncthreads();
        if (tid >= off) sums[tid] += v;
        __syncthreads();
    }
    int run = (tid == 0) ? 0 : sums[tid - 1];
    for (int i = start; i < end; i++) { offs[i] = run; run += deg[i]; }
    if (end == n) offs[n] = run;
}

__global__ void k_scatter(const int* __restrict__ src, const int* __restrict__ dst,
                          const int* __restrict__ offs, int* __restrict__ cursor,
                          int* __restrict__ csr, int E) {
    int e = blockIdx.x * blockDim.x + threadIdx.x;
    if (e >= E) return;
    int d = dst[e];
    int p = atomicAdd(cursor + d, 1);
    csr[offs[d] + p] = src[e];
}

// ---------------- layer-1 scalar aggregation (warp per node) ----------------
__global__ void k_agg0(const int* __restrict__ offs, const int* __restrict__ csr,
                       const float* __restrict__ x, float* __restrict__ agg, int N) {
    int warp = (blockIdx.x * blockDim.x + threadIdx.x) >> 5;
    int lane = threadIdx.x & 31;
    if (warp >= N) return;
    int s = offs[warp], e = offs[warp + 1];
    float acc = 0.f;
    for (int i = s + lane; i < e; i += 32) acc += __ldg(x + csr[i]);
#pragma unroll
    for (int o = 16; o; o >>= 1) acc += __shfl_xor_sync(0xffffffffu, acc, o);
    if (lane == 0) agg[warp] = acc + x[warp];   // self term
}

// ---------------- vector aggregation incl. self: out[i] = h[i] + sum_{j in N(i)} h[j] ----------------
__global__ __launch_bounds__(256) void k_agg_csr(
    const int* __restrict__ offs, const int* __restrict__ csr,
    const float* __restrict__ h, float* __restrict__ out, int N) {
    int warp = (blockIdx.x * blockDim.x + threadIdx.x) >> 5;
    int lane = threadIdx.x & 31;
    if (warp >= N) return;
    int s = offs[warp], e = offs[warp + 1];
    float4 acc = __ldg(((const float4*)(h + (size_t)warp * HN)) + lane);  // self
    int i = s;
#pragma unroll 1
    for (; i + 4 <= e; i += 4) {
        int i0 = csr[i], i1 = csr[i + 1], i2 = csr[i + 2], i3 = csr[i + 3];
        float4 v0 = __ldg(((const float4*)(h + (size_t)i0 * HN)) + lane);
        float4 v1 = __ldg(((const float4*)(h + (size_t)i1 * HN)) + lane);
        float4 v2 = __ldg(((const float4*)(h + (size_t)i2 * HN)) + lane);
        float4 v3 = __ldg(((const float4*)(h + (size_t)i3 * HN)) + lane);
        acc.x += v0.x + v1.x + v2.x + v3.x;
        acc.y += v0.y + v1.y + v2.y + v3.y;
        acc.z += v0.z + v1.z + v2.z + v3.z;
        acc.w += v0.w + v1.w + v2.w + v3.w;
    }
    for (; i < e; i++) {
        float4 v = __ldg(((const float4*)(h + (size_t)csr[i] * HN)) + lane);
        acc.x += v.x; acc.y += v.y; acc.z += v.z; acc.w += v.w;
    }
    ((float4*)(out + (size_t)warp * HN))[lane] = acc;
}

// ---------------- fused GIN layer: out = relu(relu(A@W1 + b1)@W2 + b2) ----------------
// mode 0: A is implicit rank-1 expansion of (x+agg0): tmp = relu(v_r * W1v[c] + b1[c])
// mode 1: A = pre-aggregated [nrows, 128] matrix
// smem: sW1(64K) sW2(64K) sT(32K) sA(32K) = 192KB, 1 block/SM.
extern __shared__ float s_mem[];
__global__ __launch_bounds__(256) void k_layer(
    const float* __restrict__ A, const float* __restrict__ vscal,
    const float* __restrict__ W1, const float* __restrict__ b1,
    const float* __restrict__ W2, const float* __restrict__ b2,
    float* __restrict__ Out, int nrows, int mode) {

    float* sW1 = s_mem;                    // 128*128
    float* sW2 = s_mem + HN * HN;          // 128*128
    float* sT  = s_mem + 2 * HN * HN;      // 64*128
    float* sA  = s_mem + 2 * HN * HN + TM * HN;  // 64*128 (mode1) / 64 (mode0)

    int tid  = threadIdx.x;
    int row0 = blockIdx.x * TM;
    int tr   = nrows - row0; if (tr > TM) tr = TM;

    // load W2 always
    for (int i = tid; i < HN * HN / 4; i += 256)
        ((float4*)sW2)[i] = ((const float4*)W2)[i];

    int cx = tid & 31;   // 4-col group
    int ry = tid >> 5;   // 8-row group (warp-uniform)

    if (mode == 0) {
        // sA[0..63] = x + agg0 per row (vscal already holds x+agg0)
        if (tid < TM) sA[tid] = (tid < tr) ? vscal[row0 + tid] : 0.f;
        __syncthreads();
        // tmp[r][c] = relu(v[r]*W1row[c] + b1[c]);  W1 here is the [1,128] row
        for (int i = tid; i < TM * HN / 4; i += 256) {
            int r = (i * 4) >> 7;
            int c4 = i & (HN / 4 - 1);
            float v = sA[r];
            float4 w = __ldg(((const float4*)W1) + c4);
            float4 bb = __ldg(((const float4*)b1) + c4);
            float4 t;
            t.x = fmaxf(fmaf(v, w.x, bb.x), 0.f);
            t.y = fmaxf(fmaf(v, w.y, bb.y), 0.f);
            t.z = fmaxf(fmaf(v, w.z, bb.z), 0.f);
            t.w = fmaxf(fmaf(v, w.w, bb.w), 0.f);
            ((float4*)sT)[i] = t;
        }
        __syncthreads();
    } else {
        // load W1 + A tile
        for (int i = tid; i < HN * HN / 4; i += 256)
            ((float4*)sW1)[i] = ((const float4*)W1)[i];
        for (int i = tid; i < TM * HN / 4; i += 256) {
            int r = (i * 4) >> 7;
            float4 v = make_float4(0.f, 0.f, 0.f, 0.f);
            if (r < tr)
                v = *(const float4*)(A + (size_t)(row0 + r) * HN + ((i * 4) & (HN - 1)));
            ((float4*)sA)[i] = v;
        }
        __syncthreads();

        float acc[8][4];
#pragma unroll
        for (int r = 0; r < 8; r++)
#pragma unroll
            for (int c = 0; c < 4; c++) acc[r][c] = 0.f;
        const float* sArow = sA + (size_t)(ry * 8) * HN;
#pragma unroll 4
        for (int k = 0; k < HN; k++) {
            float4 w = ((const float4*)(sW1 + (size_t)k * HN))[cx];
#pragma unroll
            for (int r = 0; r < 8; r++) {
                float a = sArow[r * HN + k];
                acc[r][0] = fmaf(a, w.x, acc[r][0]);
                acc[r][1] = fmaf(a, w.y, acc[r][1]);
                acc[r][2] = fmaf(a, w.z, acc[r][2]);
                acc[r][3] = fmaf(a, w.w, acc[r][3]);
            }
        }
        float4 bb = __ldg(((const float4*)b1) + cx);
#pragma unroll
        for (int r = 0; r < 8; r++) {
            float4 t;
            t.x = fmaxf(acc[r][0] + bb.x, 0.f);
            t.y = fmaxf(acc[r][1] + bb.y, 0.f);
            t.z = fmaxf(acc[r][2] + bb.z, 0.f);
            t.w = fmaxf(acc[r][3] + bb.w, 0.f);
            ((float4*)(sT + (size_t)(ry * 8 + r) * HN))[cx] = t;
        }
        __syncthreads();
    }

    // phase 2: Out = relu(sT @ sW2 + b2)
    float acc[8][4];
#pragma unroll
    for (int r = 0; r < 8; r++)
#pragma unroll
        for (int c = 0; c < 4; c++) acc[r][c] = 0.f;
    const float* sTrow = sT + (size_t)(ry * 8) * HN;
#pragma unroll 4
    for (int k = 0; k < HN; k++) {
        float4 w = ((const float4*)(sW2 + (size_t)k * HN))[cx];
#pragma unroll
        for (int r = 0; r < 8; r++) {
            float a = sTrow[r * HN + k];
            acc[r][0] = fmaf(a, w.x, acc[r][0]);
            acc[r][1] = fmaf(a, w.y, acc[r][1]);
            acc[r][2] = fmaf(a, w.z, acc[r][2]);
            acc[r][3] = fmaf(a, w.w, acc[r][3]);
        }
    }
    float4 bb = __ldg(((const float4*)b2) + cx);
#pragma unroll
    for (int r = 0; r < 8; r++) {
        int row = row0 + ry * 8 + r;
        if (row < nrows) {
            float4 o;
            o.x = fmaxf(acc[r][0] + bb.x, 0.f);
            o.y = fmaxf(acc[r][1] + bb.y, 0.f);
            o.z = fmaxf(acc[r][2] + bb.z, 0.f);
            o.w = fmaxf(acc[r][3] + bb.w, 0.f);
            ((float4*)(Out + (size_t)row * HN))[cx] = o;
        }
    }
}

// ---------------- pooling ----------------
__global__ void k_pool1(const float* __restrict__ h, const int* __restrict__ sub,
                        float* __restrict__ pool, int n) {
    int idx = blockIdx.x * blockDim.x + threadIdx.x;
    if (idx >= n * HN) return;
    int node = idx >> 7;
    int j    = idx & (HN - 1);
    atomicAdd(&pool[(size_t)sub[node] * HN + j], h[idx]);
}
__global__ void k_pool2(const float* __restrict__ pool, const int* __restrict__ s2g,
                        float* __restrict__ out, int s_count) {
    int idx = blockIdx.x * blockDim.x + threadIdx.x;
    if (idx >= s_count * HN) return;
    int s = idx >> 7;
    int j = idx & (HN - 1);
    atomicAdd(&out[(size_t)s2g[s] * HN + j], pool[idx]);
}

// ---------------- launch ----------------
extern "C" void kernel_launch(void* const* d_in, const int* in_sizes, int n_in,
                              void* d_out, int out_size) {
    const float* x     = (const float*)d_in[0];
    const void*  ei    = d_in[1];
    const void*  n2s   = d_in[2];
    const void*  s2g_i = d_in[3];
    const float* c1W1  = (const float*)d_in[4];
    const float* c1b1  = (const float*)d_in[5];
    const float* c1W2  = (const float*)d_in[6];
    const float* c1b2  = (const float*)d_in[7];
    const float* cW1   = (const float*)d_in[8];
    const float* cb1   = (const float*)d_in[9];
    const float* cW2   = (const float*)d_in[10];
    const float* cb2   = (const float*)d_in[11];

    int N = in_sizes[0];
    int E = in_sizes[1] / 2;
    int S = in_sizes[3];
    int G = out_size / HN;

    float *bufA, *bufB, *agg0, *pool;
    int *eiX, *sub, *s2gX, *deg, *offs, *cursor, *csr;
    cudaGetSymbolAddress((void**)&bufA,   g_bufA);
    cudaGetSymbolAddress((void**)&bufB,   g_bufB);
    cudaGetSymbolAddress((void**)&agg0,   g_agg0);
    cudaGetSymbolAddress((void**)&pool,   g_pool);
    cudaGetSymbolAddress((void**)&eiX,    g_ei);
    cudaGetSymbolAddress((void**)&sub,    g_sub);
    cudaGetSymbolAddress((void**)&s2gX,   g_s2g);
    cudaGetSymbolAddress((void**)&deg,    g_deg);
    cudaGetSymbolAddress((void**)&offs,   g_offs);
    cudaGetSymbolAddress((void**)&cursor, g_cursor);
    cudaGetSymbolAddress((void**)&csr,    g_csr);

    const int SMEM = (2 * HN * HN + 2 * TM * HN) * (int)sizeof(float);  // 192 KB
    cudaFuncSetAttribute(k_layer, cudaFuncAttributeMaxDynamicSharedMemorySize, SMEM);

    // normalize index dtypes
    k_detect<<<1, 1>>>((const unsigned long long*)ei);
    k_convert<<<(2 * E + 255) / 256, 256>>>(ei, eiX, 2 * E);
    k_convert<<<(N + 255) / 256, 256>>>(n2s, sub, N);
    k_convert<<<(S + 255) / 256, 256>>>(s2g_i, s2gX, S);

    // CSR build (dst-major)
    k_zeroi<<<(N + 255) / 256, 256>>>(deg, N);
    k_hist<<<(E + 255) / 256, 256>>>(eiX + E, deg, E);
    k_scan<<<1, 1024>>>(deg, offs, N);
    k_zeroi<<<(N + 255) / 256, 256>>>(cursor, N);
    k_scatter<<<(E + 255) / 256, 256>>>(eiX, eiX + E, offs, cursor, csr, E);

    int gblocks = (N + TM - 1) / TM;
    int ablocks = (N * 32 + 255) / 256;

    // layer 1: scalar agg (includes self), fused expansion + GEMM2
    k_agg0<<<ablocks, 256>>>(offs, csr, x, agg0, N);
    k_layer<<<gblocks, 256, SMEM>>>(nullptr, agg0, c1W1, c1b1, c1W2, c1b2, bufB, N, 0);

    // layers 2..3: CSR agg (includes self) then fused dual GEMM
    for (int i = 0; i < 2; i++) {
        k_agg_csr<<<ablocks, 256>>>(offs, csr, bufB, bufA, N);
        k_layer<<<gblocks, 256, SMEM>>>(bufA, nullptr,
                                        cW1 + (size_t)i * HN * HN, cb1 + (size_t)i * HN,
                                        cW2 + (size_t)i * HN * HN, cb2 + (size_t)i * HN,
                                        bufB, N, 1);
    }

    // pooling: nodes -> subgraphs -> graphs
    k_zero4<<<((S * HN / 4) + 255) / 256, 256>>>(pool, S * HN / 4);
    k_zero4<<<((G * HN / 4) + 255) / 256, 256>>>((float*)d_out, G * HN / 4);
    k_pool1<<<((size_t)N * HN + 255) / 256, 256>>>(bufB, sub, pool, N);
    k_pool2<<<((size_t)S * HN + 255) / 256, 256>>>(pool, s2gX, (float*)d_out, S);
}

// round 4
// speedup vs baseline: 1.7297x; 1.0216x over previous
#include <cuda_runtime.h>
#include <cstdint>

#define HN   128
#define MAXN 100000
#define MAXE 1600000
#define MAXS 10000
#define TM   64
#define TSTRIDE 66   // padded transposed-tile stride (floats): even (8B align) + conflict spread

// ---------------- scratch (static device globals; no allocation) ----------------
__device__ float g_bufA[(size_t)MAXN * HN];
__device__ float g_bufB[(size_t)MAXN * HN];
__device__ float g_agg0[MAXN];
__device__ int   g_ei[2 * MAXE];
__device__ int   g_sub[MAXN];
__device__ int   g_s2g[MAXS];
__device__ int   g_comp[MAXN];
__device__ int   g_deg[MAXN];
__device__ int   g_offs[MAXN + 1];
__device__ int   g_cursor[MAXN];
__device__ int   g_csr[MAXE];
__device__ int   g_is64;

// ---------------- f32x2 helpers ----------------
__device__ __forceinline__ unsigned long long fma2(unsigned long long a, unsigned long long b,
                                                   unsigned long long c) {
    unsigned long long d;
    asm("fma.rn.f32x2 %0, %1, %2, %3;" : "=l"(d) : "l"(a), "l"(b), "l"(c));
    return d;
}
__device__ __forceinline__ unsigned long long packf2(float x, float y) {
    unsigned long long d;
    asm("mov.b64 %0, {%1, %2};" : "=l"(d)
        : "r"(__float_as_uint(x)), "r"(__float_as_uint(y)));
    return d;
}
__device__ __forceinline__ void unpackf2(unsigned long long v, float& lo, float& hi) {
    unsigned int a, b;
    asm("mov.b64 {%0, %1}, %2;" : "=r"(a), "=r"(b) : "l"(v));
    lo = __uint_as_float(a); hi = __uint_as_float(b);
}

// ---------------- index dtype detection + normalization ----------------
__global__ void k_detect(const unsigned long long* __restrict__ p) {
    if (blockIdx.x == 0 && threadIdx.x == 0) {
        int is64 = 1;
        for (int i = 0; i < 64; i++)
            if (p[i] >> 32) { is64 = 0; break; }
        g_is64 = is64;
    }
}
__global__ void k_convert(const void* __restrict__ in, int* __restrict__ out, int n) {
    int i = blockIdx.x * blockDim.x + threadIdx.x;
    if (i >= n) return;
    if (g_is64) out[i] = (int)(((const long long*)in)[i]);
    else        out[i] = ((const int*)in)[i];
}

// ---------------- utility ----------------
__global__ void k_zero4(float* __restrict__ p, int n4) {
    int i = blockIdx.x * blockDim.x + threadIdx.x;
    if (i < n4) ((float4*)p)[i] = make_float4(0.f, 0.f, 0.f, 0.f);
}
__global__ void k_zeroi(int* __restrict__ p, int n) {
    int i = blockIdx.x * blockDim.x + threadIdx.x;
    if (i < n) p[i] = 0;
}

// ---------------- CSR build ----------------
__global__ void k_hist(const int* __restrict__ dst, int* __restrict__ deg, int E) {
    int e = blockIdx.x * blockDim.x + threadIdx.x;
    if (e < E) atomicAdd(deg + dst[e], 1);
}
__global__ void k_scan(const int* __restrict__ deg, int* __restrict__ offs, int n) {
    __shared__ int sums[1024];
    int tid = threadIdx.x;
    int chunk = (n + 1023) / 1024;
    int start = tid * chunk;
    int end   = start + chunk; if (end > n) end = n;
    int s = 0;
    for (int i = start; i < end; i++) s += deg[i];
    sums[tid] = s;
    __syncthreads();
    for (int off = 1; off < 1024; off <<= 1) {
        int v = 0;
        if (tid >= off) v = sums[tid - off];
        __syncthreads();
        if (tid >= off) sums[tid] += v;
        __syncthreads();
    }
    int run = (tid == 0) ? 0 : sums[tid - 1];
    for (int i = start; i < end; i++) { offs[i] = run; run += deg[i]; }
    if (end == n) offs[n] = run;
}
__global__ void k_scatter(const int* __restrict__ src, const int* __restrict__ dst,
                          const int* __restrict__ offs, int* __restrict__ cursor,
                          int* __restrict__ csr, int E) {
    int e = blockIdx.x * blockDim.x + threadIdx.x;
    if (e >= E) return;
    int d = dst[e];
    int p = atomicAdd(cursor + d, 1);
    csr[offs[d] + p] = src[e];
}

// ---------------- layer-1 scalar aggregation ----------------
__global__ void k_agg0(const int* __restrict__ offs, const int* __restrict__ csr,
                       const float* __restrict__ x, float* __restrict__ agg, int N) {
    int warp = (blockIdx.x * blockDim.x + threadIdx.x) >> 5;
    int lane = threadIdx.x & 31;
    if (warp >= N) return;
    int s = offs[warp], e = offs[warp + 1];
    float acc = 0.f;
    for (int i = s + lane; i < e; i += 32) acc += __ldg(x + csr[i]);
#pragma unroll
    for (int o = 16; o; o >>= 1) acc += __shfl_xor_sync(0xffffffffu, acc, o);
    if (lane == 0) agg[warp] = acc + x[warp];
}

// ---------------- vector aggregation incl. self ----------------
__global__ __launch_bounds__(256) void k_agg_csr(
    const int* __restrict__ offs, const int* __restrict__ csr,
    const float* __restrict__ h, float* __restrict__ out, int N) {
    int warp = (blockIdx.x * blockDim.x + threadIdx.x) >> 5;
    int lane = threadIdx.x & 31;
    if (warp >= N) return;
    int s = offs[warp], e = offs[warp + 1];
    float4 acc = __ldg(((const float4*)(h + (size_t)warp * HN)) + lane);
    int i = s;
#pragma unroll 1
    for (; i + 4 <= e; i += 4) {
        int i0 = csr[i], i1 = csr[i + 1], i2 = csr[i + 2], i3 = csr[i + 3];
        float4 v0 = __ldg(((const float4*)(h + (size_t)i0 * HN)) + lane);
        float4 v1 = __ldg(((const float4*)(h + (size_t)i1 * HN)) + lane);
        float4 v2 = __ldg(((const float4*)(h + (size_t)i2 * HN)) + lane);
        float4 v3 = __ldg(((const float4*)(h + (size_t)i3 * HN)) + lane);
        acc.x += v0.x + v1.x + v2.x + v3.x;
        acc.y += v0.y + v1.y + v2.y + v3.y;
        acc.z += v0.z + v1.z + v2.z + v3.z;
        acc.w += v0.w + v1.w + v2.w + v3.w;
    }
    for (; i < e; i++) {
        float4 v = __ldg(((const float4*)(h + (size_t)csr[i] * HN)) + lane);
        acc.x += v.x; acc.y += v.y; acc.z += v.z; acc.w += v.w;
    }
    ((float4*)(out + (size_t)warp * HN))[lane] = acc;
}

// ---------------- fused GIN layer with f32x2 GEMMs ----------------
// smem: sW1(64K) sW2(64K) sTt(128*66*4=33K) sAt(33K) ~ 194KB
// Activation tiles stored TRANSPOSED: sXt[k*TSTRIDE + row], so a row-pair at
// fixed k is one LDS.64 (warp-broadcast). acc packs two rows per 64-bit reg.
extern __shared__ float s_mem[];

__device__ __forceinline__ void gemm_f32x2(const float* __restrict__ sW,
                                           const float* __restrict__ sXt,
                                           int cx, int ry,
                                           unsigned long long accp[4][4]) {
#pragma unroll
    for (int p = 0; p < 4; p++)
#pragma unroll
        for (int c = 0; c < 4; c++) accp[p][c] = 0ULL;

#pragma unroll 4
    for (int k = 0; k < HN; k++) {
        float4 w = ((const float4*)(sW + (size_t)k * HN))[cx];
        unsigned long long wd0 = packf2(w.x, w.x);
        unsigned long long wd1 = packf2(w.y, w.y);
        unsigned long long wd2 = packf2(w.z, w.z);
        unsigned long long wd3 = packf2(w.w, w.w);
        const unsigned long long* ap =
            (const unsigned long long*)(sXt + (size_t)k * TSTRIDE + ry * 8);
        unsigned long long a0 = ap[0], a1 = ap[1], a2 = ap[2], a3 = ap[3];
        accp[0][0] = fma2(a0, wd0, accp[0][0]);
        accp[0][1] = fma2(a0, wd1, accp[0][1]);
        accp[0][2] = fma2(a0, wd2, accp[0][2]);
        accp[0][3] = fma2(a0, wd3, accp[0][3]);
        accp[1][0] = fma2(a1, wd0, accp[1][0]);
        accp[1][1] = fma2(a1, wd1, accp[1][1]);
        accp[1][2] = fma2(a1, wd2, accp[1][2]);
        accp[1][3] = fma2(a1, wd3, accp[1][3]);
        accp[2][0] = fma2(a2, wd0, accp[2][0]);
        accp[2][1] = fma2(a2, wd1, accp[2][1]);
        accp[2][2] = fma2(a2, wd2, accp[2][2]);
        accp[2][3] = fma2(a2, wd3, accp[2][3]);
        accp[3][0] = fma2(a3, wd0, accp[3][0]);
        accp[3][1] = fma2(a3, wd1, accp[3][1]);
        accp[3][2] = fma2(a3, wd2, accp[3][2]);
        accp[3][3] = fma2(a3, wd3, accp[3][3]);
    }
}

__global__ __launch_bounds__(256) void k_layer(
    const float* __restrict__ A, const float* __restrict__ vscal,
    const float* __restrict__ W1, const float* __restrict__ b1,
    const float* __restrict__ W2, const float* __restrict__ b2,
    float* __restrict__ Out, int nrows, int mode) {

    float* sW1 = s_mem;                           // 128*128
    float* sW2 = s_mem + HN * HN;                 // 128*128
    float* sTt = s_mem + 2 * HN * HN;             // 128*66 transposed tmp
    float* sAt = sTt + HN * TSTRIDE;              // 128*66 transposed A (mode1) / v (mode0)

    int tid  = threadIdx.x;
    int row0 = blockIdx.x * TM;
    int tr   = nrows - row0; if (tr > TM) tr = TM;
    int cx = tid & 31;   // 4-col group
    int ry = tid >> 5;   // 8-row group (warp-uniform)

    for (int i = tid; i < HN * HN / 4; i += 256)
        ((float4*)sW2)[i] = ((const float4*)W2)[i];

    if (mode == 0) {
        if (tid < TM) sAt[tid] = (tid < tr) ? vscal[row0 + tid] : 0.f;
        __syncthreads();
        // tmp (transposed): sTt[c*TS + r] = relu(v[r]*W1[c] + b1[c])
        for (int i = tid; i < TM * HN / 4; i += 256) {
            int r  = i >> 5;
            int c0 = (i & 31) * 4;
            float v = sAt[r];
            float4 w  = __ldg((const float4*)(W1 + c0));
            float4 bb = __ldg((const float4*)(b1 + c0));
            sTt[(c0 + 0) * TSTRIDE + r] = fmaxf(fmaf(v, w.x, bb.x), 0.f);
            sTt[(c0 + 1) * TSTRIDE + r] = fmaxf(fmaf(v, w.y, bb.y), 0.f);
            sTt[(c0 + 2) * TSTRIDE + r] = fmaxf(fmaf(v, w.z, bb.z), 0.f);
            sTt[(c0 + 3) * TSTRIDE + r] = fmaxf(fmaf(v, w.w, bb.w), 0.f);
        }
        __syncthreads();
    } else {
        for (int i = tid; i < HN * HN / 4; i += 256)
            ((float4*)sW1)[i] = ((const float4*)W1)[i];
        // load A tile transposed
        for (int i = tid; i < TM * HN / 4; i += 256) {
            int r  = i >> 5;
            int c0 = (i & 31) * 4;
            float4 v = make_float4(0.f, 0.f, 0.f, 0.f);
            if (r < tr)
                v = *(const float4*)(A + (size_t)(row0 + r) * HN + c0);
            sAt[(c0 + 0) * TSTRIDE + r] = v.x;
            sAt[(c0 + 1) * TSTRIDE + r] = v.y;
            sAt[(c0 + 2) * TSTRIDE + r] = v.z;
            sAt[(c0 + 3) * TSTRIDE + r] = v.w;
        }
        __syncthreads();

        unsigned long long accp[4][4];
        gemm_f32x2(sW1, sAt, cx, ry, accp);

        float4 bb = __ldg(((const float4*)b1) + cx);
#pragma unroll
        for (int p = 0; p < 4; p++) {
            float lo[4], hi[4];
#pragma unroll
            for (int c = 0; c < 4; c++) unpackf2(accp[p][c], lo[c], hi[c]);
            int rA = ry * 8 + 2 * p, rB = rA + 1;
            sTt[(4 * cx + 0) * TSTRIDE + rA] = fmaxf(lo[0] + bb.x, 0.f);
            sTt[(4 * cx + 1) * TSTRIDE + rA] = fmaxf(lo[1] + bb.y, 0.f);
            sTt[(4 * cx + 2) * TSTRIDE + rA] = fmaxf(lo[2] + bb.z, 0.f);
            sTt[(4 * cx + 3) * TSTRIDE + rA] = fmaxf(lo[3] + bb.w, 0.f);
            sTt[(4 * cx + 0) * TSTRIDE + rB] = fmaxf(hi[0] + bb.x, 0.f);
            sTt[(4 * cx + 1) * TSTRIDE + rB] = fmaxf(hi[1] + bb.y, 0.f);
            sTt[(4 * cx + 2) * TSTRIDE + rB] = fmaxf(hi[2] + bb.z, 0.f);
            sTt[(4 * cx + 3) * TSTRIDE + rB] = fmaxf(hi[3] + bb.w, 0.f);
        }
        __syncthreads();
    }

    // phase 2: Out = relu(tmp @ W2 + b2)
    unsigned long long accp[4][4];
    gemm_f32x2(sW2, sTt, cx, ry, accp);

    float4 bb = __ldg(((const float4*)b2) + cx);
#pragma unroll
    for (int p = 0; p < 4; p++) {
        float lo[4], hi[4];
#pragma unroll
        for (int c = 0; c < 4; c++) unpackf2(accp[p][c], lo[c], hi[c]);
        int rA = row0 + ry * 8 + 2 * p;
        if (rA < nrows) {
            float4 o;
            o.x = fmaxf(lo[0] + bb.x, 0.f);
            o.y = fmaxf(lo[1] + bb.y, 0.f);
            o.z = fmaxf(lo[2] + bb.z, 0.f);
            o.w = fmaxf(lo[3] + bb.w, 0.f);
            ((float4*)(Out + (size_t)rA * HN))[cx] = o;
        }
        if (rA + 1 < nrows) {
            float4 o;
            o.x = fmaxf(hi[0] + bb.x, 0.f);
            o.y = fmaxf(hi[1] + bb.y, 0.f);
            o.z = fmaxf(hi[2] + bb.z, 0.f);
            o.w = fmaxf(hi[3] + bb.w, 0.f);
            ((float4*)(Out + (size_t)(rA + 1) * HN))[cx] = o;
        }
    }
}

// ---------------- pooling: direct nodes -> graphs (comp sorted) ----------------
__global__ void k_comp(const int* __restrict__ sub, const int* __restrict__ s2g,
                       int* __restrict__ comp, int n) {
    int i = blockIdx.x * blockDim.x + threadIdx.x;
    if (i < n) comp[i] = s2g[sub[i]];
}
__global__ void k_pool(const float* __restrict__ h, const int* __restrict__ comp,
                       float* __restrict__ out, int N) {
    int j = threadIdx.x;  // 0..127
    int per = (N + gridDim.x - 1) / gridDim.x;
    int n0 = blockIdx.x * per;
    int n1 = n0 + per; if (n1 > N) n1 = N;
    if (n0 >= n1) return;
    float acc = 0.f;
    int cur = __ldg(comp + n0);
    for (int i = n0; i < n1; i++) {
        int c = __ldg(comp + i);
        if (c != cur) {
            atomicAdd(out + (size_t)cur * HN + j, acc);
            acc = 0.f; cur = c;
        }
        acc += __ldg(h + (size_t)i * HN + j);
    }
    atomicAdd(out + (size_t)cur * HN + j, acc);
}

// ---------------- launch ----------------
extern "C" void kernel_launch(void* const* d_in, const int* in_sizes, int n_in,
                              void* d_out, int out_size) {
    const float* x     = (const float*)d_in[0];
    const void*  ei    = d_in[1];
    const void*  n2s   = d_in[2];
    const void*  s2g_i = d_in[3];
    const float* c1W1  = (const float*)d_in[4];
    const float* c1b1  = (const float*)d_in[5];
    const float* c1W2  = (const float*)d_in[6];
    const float* c1b2  = (const float*)d_in[7];
    const float* cW1   = (const float*)d_in[8];
    const float* cb1   = (const float*)d_in[9];
    const float* cW2   = (const float*)d_in[10];
    const float* cb2   = (const float*)d_in[11];

    int N = in_sizes[0];
    int E = in_sizes[1] / 2;
    int S = in_sizes[3];
    int G = out_size / HN;

    float *bufA, *bufB, *agg0;
    int *eiX, *sub, *s2gX, *comp, *deg, *offs, *cursor, *csr;
    cudaGetSymbolAddress((void**)&bufA,   g_bufA);
    cudaGetSymbolAddress((void**)&bufB,   g_bufB);
    cudaGetSymbolAddress((void**)&agg0,   g_agg0);
    cudaGetSymbolAddress((void**)&eiX,    g_ei);
    cudaGetSymbolAddress((void**)&sub,    g_sub);
    cudaGetSymbolAddress((void**)&s2gX,   g_s2g);
    cudaGetSymbolAddress((void**)&comp,   g_comp);
    cudaGetSymbolAddress((void**)&deg,    g_deg);
    cudaGetSymbolAddress((void**)&offs,   g_offs);
    cudaGetSymbolAddress((void**)&cursor, g_cursor);
    cudaGetSymbolAddress((void**)&csr,    g_csr);

    const int SMEM = (2 * HN * HN + 2 * HN * TSTRIDE) * (int)sizeof(float);  // ~194 KB
    cudaFuncSetAttribute(k_layer, cudaFuncAttributeMaxDynamicSharedMemorySize, SMEM);

    // normalize index dtypes
    k_detect<<<1, 1>>>((const unsigned long long*)ei);
    k_convert<<<(2 * E + 255) / 256, 256>>>(ei, eiX, 2 * E);
    k_convert<<<(N + 255) / 256, 256>>>(n2s, sub, N);
    k_convert<<<(S + 255) / 256, 256>>>(s2g_i, s2gX, S);
    k_comp<<<(N + 255) / 256, 256>>>(sub, s2gX, comp, N);

    // CSR build (dst-major)
    k_zeroi<<<(N + 255) / 256, 256>>>(deg, N);
    k_hist<<<(E + 255) / 256, 256>>>(eiX + E, deg, E);
    k_scan<<<1, 1024>>>(deg, offs, N);
    k_zeroi<<<(N + 255) / 256, 256>>>(cursor, N);
    k_scatter<<<(E + 255) / 256, 256>>>(eiX, eiX + E, offs, cursor, csr, E);

    int gblocks = (N + TM - 1) / TM;
    int ablocks = (N * 32 + 255) / 256;

    // layer 1
    k_agg0<<<ablocks, 256>>>(offs, csr, x, agg0, N);
    k_layer<<<gblocks, 256, SMEM>>>(nullptr, agg0, c1W1, c1b1, c1W2, c1b2, bufB, N, 0);

    // layers 2..3
    for (int i = 0; i < 2; i++) {
        k_agg_csr<<<ablocks, 256>>>(offs, csr, bufB, bufA, N);
        k_layer<<<gblocks, 256, SMEM>>>(bufA, nullptr,
                                        cW1 + (size_t)i * HN * HN, cb1 + (size_t)i * HN,
                                        cW2 + (size_t)i * HN * HN, cb2 + (size_t)i * HN,
                                        bufB, N, 1);
    }

    // pooling: nodes -> graphs via composed index
    k_zero4<<<((G * HN / 4) + 255) / 256, 256>>>((float*)d_out, G * HN / 4);
    k_pool<<<512, HN>>>(bufB, comp, (float*)d_out, N);
}

// round 5
// speedup vs baseline: 3.0010x; 1.7350x over previous
#include <cuda_runtime.h>
#include <cuda_bf16.h>
#include <cstdint>

#define HN   128
#define MAXN 100000
#define MAXE 1600000
#define MAXS 10000
#define TM   64
#define WS   136          // padded bf16 plane stride (rows land 4 banks apart for LDSM)
#define PLANE (HN * WS)   // 17408 bf16 elems per plane

// ---------------- scratch (static device globals; no allocation) ----------------
__device__ float g_bufA[(size_t)MAXN * HN];
__device__ float g_bufB[(size_t)MAXN * HN];
__device__ float g_agg0[MAXN];
__device__ int   g_ei[2 * MAXE];
__device__ int   g_sub[MAXN];
__device__ int   g_s2g[MAXS];
__device__ int   g_comp[MAXN];
__device__ int   g_deg[MAXN];
__device__ int   g_offs[MAXN + 1];
__device__ int   g_cursor[MAXN];
__device__ int   g_csr[MAXE];
__device__ int   g_is64;
__device__ __nv_bfloat16 g_wsplit[5 * 2 * PLANE];   // 5 matrices x {hi,lo}

// ---------------- helpers ----------------
__device__ __forceinline__ uint32_t sptr(const void* p) {
    return (uint32_t)__cvta_generic_to_shared(p);
}
__device__ __forceinline__ void splitf(float x, __nv_bfloat16& h, __nv_bfloat16& l) {
    h = __float2bfloat16(x);
    l = __float2bfloat16(x - __bfloat162float(h));
}
__device__ __forceinline__ void ldsm4(uint32_t a, uint32_t& r0, uint32_t& r1,
                                      uint32_t& r2, uint32_t& r3) {
    asm volatile("ldmatrix.sync.aligned.m8n8.x4.shared.b16 {%0,%1,%2,%3},[%4];"
                 : "=r"(r0), "=r"(r1), "=r"(r2), "=r"(r3) : "r"(a));
}
__device__ __forceinline__ void ldsm4t(uint32_t a, uint32_t& r0, uint32_t& r1,
                                       uint32_t& r2, uint32_t& r3) {
    asm volatile("ldmatrix.sync.aligned.m8n8.x4.trans.shared.b16 {%0,%1,%2,%3},[%4];"
                 : "=r"(r0), "=r"(r1), "=r"(r2), "=r"(r3) : "r"(a));
}
__device__ __forceinline__ void mma16816(float* c, uint32_t a0, uint32_t a1, uint32_t a2,
                                         uint32_t a3, uint32_t b0, uint32_t b1) {
    asm volatile(
        "mma.sync.aligned.m16n8k16.row.col.f32.bf16.bf16.f32 "
        "{%0,%1,%2,%3},{%4,%5,%6,%7},{%8,%9},{%0,%1,%2,%3};"
        : "+f"(c[0]), "+f"(c[1]), "+f"(c[2]), "+f"(c[3])
        : "r"(a0), "r"(a1), "r"(a2), "r"(a3), "r"(b0), "r"(b1));
}

// ---------------- index dtype detection + normalization ----------------
__global__ void k_detect(const unsigned long long* __restrict__ p) {
    if (blockIdx.x == 0 && threadIdx.x == 0) {
        int is64 = 1;
        for (int i = 0; i < 64; i++)
            if (p[i] >> 32) { is64 = 0; break; }
        g_is64 = is64;
    }
}
__global__ void k_convert(const void* __restrict__ in, int* __restrict__ out, int n) {
    int i = blockIdx.x * blockDim.x + threadIdx.x;
    if (i >= n) return;
    if (g_is64) out[i] = (int)(((const long long*)in)[i]);
    else        out[i] = ((const int*)in)[i];
}

// ---------------- utility ----------------
__global__ void k_zero4(float* __restrict__ p, int n4) {
    int i = blockIdx.x * blockDim.x + threadIdx.x;
    if (i < n4) ((float4*)p)[i] = make_float4(0.f, 0.f, 0.f, 0.f);
}
__global__ void k_zeroi(int* __restrict__ p, int n) {
    int i = blockIdx.x * blockDim.x + threadIdx.x;
    if (i < n) p[i] = 0;
}

// ---------------- W split: fp32 [128,128] -> bf16 hi/lo planes (stride WS) ----------------
__global__ void k_splitW(const float* __restrict__ W, __nv_bfloat16* __restrict__ dh,
                         __nv_bfloat16* __restrict__ dl) {
    int i = blockIdx.x * blockDim.x + threadIdx.x;
    if (i >= HN * HN) return;
    int k = i >> 7, n = i & 127;
    __nv_bfloat16 h, l;
    splitf(W[i], h, l);
    dh[k * WS + n] = h;
    dl[k * WS + n] = l;
}

// ---------------- CSR build ----------------
__global__ void k_hist(const int* __restrict__ dst, int* __restrict__ deg, int E) {
    int e = blockIdx.x * blockDim.x + threadIdx.x;
    if (e < E) atomicAdd(deg + dst[e], 1);
}
__global__ void k_scan(const int* __restrict__ deg, int* __restrict__ offs, int n) {
    __shared__ int sums[1024];
    int tid = threadIdx.x;
    int chunk = (n + 1023) / 1024;
    int start = tid * chunk;
    int end   = start + chunk; if (end > n) end = n;
    int s = 0;
    for (int i = start; i < end; i++) s += deg[i];
    sums[tid] = s;
    __syncthreads();
    for (int off = 1; off < 1024; off <<= 1) {
        int v = 0;
        if (tid >= off) v = sums[tid - off];
        __syncthreads();
        if (tid >= off) sums[tid] += v;
        __syncthreads();
    }
    int run = (tid == 0) ? 0 : sums[tid - 1];
    for (int i = start; i < end; i++) { offs[i] = run; run += deg[i]; }
    if (end == n) offs[n] = run;
}
__global__ void k_scatter(const int* __restrict__ src, const int* __restrict__ dst,
                          const int* __restrict__ offs, int* __restrict__ cursor,
                          int* __restrict__ csr, int E) {
    int e = blockIdx.x * blockDim.x + threadIdx.x;
    if (e >= E) return;
    int d = dst[e];
    int p = atomicAdd(cursor + d, 1);
    csr[offs[d] + p] = src[e];
}

// ---------------- layer-1 scalar aggregation ----------------
__global__ void k_agg0(const int* __restrict__ offs, const int* __restrict__ csr,
                       const float* __restrict__ x, float* __restrict__ agg, int N) {
    int warp = (blockIdx.x * blockDim.x + threadIdx.x) >> 5;
    int lane = threadIdx.x & 31;
    if (warp >= N) return;
    int s = offs[warp], e = offs[warp + 1];
    float acc = 0.f;
    for (int i = s + lane; i < e; i += 32) acc += __ldg(x + csr[i]);
#pragma unroll
    for (int o = 16; o; o >>= 1) acc += __shfl_xor_sync(0xffffffffu, acc, o);
    if (lane == 0) agg[warp] = acc + x[warp];
}

// ---------------- vector aggregation incl. self ----------------
__global__ __launch_bounds__(256) void k_agg_csr(
    const int* __restrict__ offs, const int* __restrict__ csr,
    const float* __restrict__ h, float* __restrict__ out, int N) {
    int warp = (blockIdx.x * blockDim.x + threadIdx.x) >> 5;
    int lane = threadIdx.x & 31;
    if (warp >= N) return;
    int s = offs[warp], e = offs[warp + 1];
    float4 acc = __ldg(((const float4*)(h + (size_t)warp * HN)) + lane);
    int i = s;
#pragma unroll 1
    for (; i + 4 <= e; i += 4) {
        int i0 = csr[i], i1 = csr[i + 1], i2 = csr[i + 2], i3 = csr[i + 3];
        float4 v0 = __ldg(((const float4*)(h + (size_t)i0 * HN)) + lane);
        float4 v1 = __ldg(((const float4*)(h + (size_t)i1 * HN)) + lane);
        float4 v2 = __ldg(((const float4*)(h + (size_t)i2 * HN)) + lane);
        float4 v3 = __ldg(((const float4*)(h + (size_t)i3 * HN)) + lane);
        acc.x += v0.x + v1.x + v2.x + v3.x;
        acc.y += v0.y + v1.y + v2.y + v3.y;
        acc.z += v0.z + v1.z + v2.z + v3.z;
        acc.w += v0.w + v1.w + v2.w + v3.w;
    }
    for (; i < e; i++) {
        float4 v = __ldg(((const float4*)(h + (size_t)csr[i] * HN)) + lane);
        acc.x += v.x; acc.y += v.y; acc.z += v.z; acc.w += v.w;
    }
    ((float4*)(out + (size_t)warp * HN))[lane] = acc;
}

// ---------------- MMA phase: acc[8][4] += split-bf16 A[64,128] @ B[128,128] ----------------
__device__ __forceinline__ void mma_phase(
    const __nv_bfloat16* Ah, const __nv_bfloat16* Al,
    const __nv_bfloat16* Bh, const __nv_bfloat16* Bl,
    int mrow0, int nbase, int lane, float acc[8][4]) {
#pragma unroll
    for (int j = 0; j < 8; j++)
#pragma unroll
        for (int c = 0; c < 4; c++) acc[j][c] = 0.f;

    int aoff = (mrow0 + (lane & 15)) * WS + ((lane >> 4) << 3);
    int brow = (lane & 15) * WS;
    int bn   = (lane >> 4) << 3;

#pragma unroll
    for (int kt = 0; kt < 8; kt++) {
        uint32_t ah0, ah1, ah2, ah3, al0, al1, al2, al3;
        ldsm4(sptr(Ah + aoff + kt * 16), ah0, ah1, ah2, ah3);
        ldsm4(sptr(Al + aoff + kt * 16), al0, al1, al2, al3);
#pragma unroll
        for (int jj = 0; jj < 4; jj++) {
            int nj = nbase + jj * 16;
            uint32_t bh0, bh1, bh2, bh3, bl0, bl1, bl2, bl3;
            ldsm4t(sptr(Bh + kt * 16 * WS + brow + nj + bn), bh0, bh1, bh2, bh3);
            ldsm4t(sptr(Bl + kt * 16 * WS + brow + nj + bn), bl0, bl1, bl2, bl3);
            mma16816(acc[2 * jj],     ah0, ah1, ah2, ah3, bh0, bh1);
            mma16816(acc[2 * jj],     ah0, ah1, ah2, ah3, bl0, bl1);
            mma16816(acc[2 * jj],     al0, al1, al2, al3, bh0, bh1);
            mma16816(acc[2 * jj + 1], ah0, ah1, ah2, ah3, bh2, bh3);
            mma16816(acc[2 * jj + 1], ah0, ah1, ah2, ah3, bl2, bl3);
            mma16816(acc[2 * jj + 1], al0, al1, al2, al3, bh2, bh3);
        }
    }
}

// ---------------- fused GIN layer (persistent blocks, tensor-core GEMMs) ----------------
// smem bf16 planes: W1h W1l W2h W2l (128xWS each) + Ah Al Th Tl (64xWS each)
#define OFF_W1H 0
#define OFF_W1L (1 * PLANE)
#define OFF_W2H (2 * PLANE)
#define OFF_W2L (3 * PLANE)
#define OFF_AH  (4 * PLANE)
#define OFF_AL  (4 * PLANE + TM * WS)
#define OFF_TH  (4 * PLANE + 2 * TM * WS)
#define OFF_TL  (4 * PLANE + 3 * TM * WS)
#define SMEM_ELEMS (4 * PLANE + 4 * TM * WS)

extern __shared__ __nv_bfloat16 sb[];

__global__ __launch_bounds__(256) void k_layer(
    const float* __restrict__ A, const float* __restrict__ vscal,
    const float* __restrict__ W1v,
    const __nv_bfloat16* __restrict__ W1h, const __nv_bfloat16* __restrict__ W1l,
    const float* __restrict__ b1,
    const __nv_bfloat16* __restrict__ W2h, const __nv_bfloat16* __restrict__ W2l,
    const float* __restrict__ b2,
    float* __restrict__ Out, int nrows, int mode) {

    __shared__ float sv[TM];
    int tid  = threadIdx.x;
    int lane = tid & 31;
    int w    = tid >> 5;
    int mrow0 = (w >> 1) * 16;
    int nbase = (w & 1) * 64;

    __nv_bfloat16* sW1h = sb + OFF_W1H;
    __nv_bfloat16* sW1l = sb + OFF_W1L;
    __nv_bfloat16* sW2h = sb + OFF_W2H;
    __nv_bfloat16* sW2l = sb + OFF_W2L;
    __nv_bfloat16* sAh  = sb + OFF_AH;
    __nv_bfloat16* sAl  = sb + OFF_AL;
    __nv_bfloat16* sTh  = sb + OFF_TH;
    __nv_bfloat16* sTl  = sb + OFF_TL;

    // load W planes once (persistent block)
    const int U4 = PLANE * 2 / 16;   // uint4 per plane
    for (int i = tid; i < U4; i += 256) {
        ((uint4*)sW2h)[i] = ((const uint4*)W2h)[i];
        ((uint4*)sW2l)[i] = ((const uint4*)W2l)[i];
        if (mode == 1) {
            ((uint4*)sW1h)[i] = ((const uint4*)W1h)[i];
            ((uint4*)sW1l)[i] = ((const uint4*)W1l)[i];
        }
    }

    int ntiles = (nrows + TM - 1) / TM;
    for (int t = blockIdx.x; t < ntiles; t += gridDim.x) {
        int row0 = t * TM;
        int tr = nrows - row0; if (tr > TM) tr = TM;
        __syncthreads();   // W ready / previous tile's smem reads done

        if (mode == 0) {
            if (tid < TM) sv[tid] = (tid < tr) ? vscal[row0 + tid] : 0.f;
            __syncthreads();
            for (int i = tid; i < TM * HN; i += 256) {
                int r = i >> 7, c = i & 127;
                float v = fmaxf(fmaf(sv[r], __ldg(W1v + c), __ldg(b1 + c)), 0.f);
                __nv_bfloat16 h, l;
                splitf(v, h, l);
                sTh[r * WS + c] = h;
                sTl[r * WS + c] = l;
            }
            __syncthreads();
        } else {
            // load A tile, split to bf16 planes
            for (int i = tid; i < TM * HN / 4; i += 256) {
                int e = i * 4, r = e >> 7, c = e & 127;
                float4 v = make_float4(0.f, 0.f, 0.f, 0.f);
                if (r < tr) v = *(const float4*)(A + (size_t)(row0 + r) * HN + c);
                __nv_bfloat16 h, l;
                splitf(v.x, h, l); sAh[r * WS + c]     = h; sAl[r * WS + c]     = l;
                splitf(v.y, h, l); sAh[r * WS + c + 1] = h; sAl[r * WS + c + 1] = l;
                splitf(v.z, h, l); sAh[r * WS + c + 2] = h; sAl[r * WS + c + 2] = l;
                splitf(v.w, h, l); sAh[r * WS + c + 3] = h; sAl[r * WS + c + 3] = l;
            }
            __syncthreads();

            float acc[8][4];
            mma_phase(sAh, sAl, sW1h, sW1l, mrow0, nbase, lane, acc);

            // bias + relu -> split into sT
            int r0 = mrow0 + (lane >> 2);
#pragma unroll
            for (int j = 0; j < 8; j++) {
                int c = nbase + 8 * j + (lane & 3) * 2;
                float bx = __ldg(b1 + c), by = __ldg(b1 + c + 1);
                float v00 = fmaxf(acc[j][0] + bx, 0.f);
                float v01 = fmaxf(acc[j][1] + by, 0.f);
                float v10 = fmaxf(acc[j][2] + bx, 0.f);
                float v11 = fmaxf(acc[j][3] + by, 0.f);
                __nv_bfloat162 ph, pl;
                splitf(v00, ph.x, pl.x); splitf(v01, ph.y, pl.y);
                *(__nv_bfloat162*)(sTh + r0 * WS + c) = ph;
                *(__nv_bfloat162*)(sTl + r0 * WS + c) = pl;
                splitf(v10, ph.x, pl.x); splitf(v11, ph.y, pl.y);
                *(__nv_bfloat162*)(sTh + (r0 + 8) * WS + c) = ph;
                *(__nv_bfloat162*)(sTl + (r0 + 8) * WS + c) = pl;
            }
            __syncthreads();
        }

        // phase 2: Out = relu(T @ W2 + b2)
        float acc[8][4];
        mma_phase(sTh, sTl, sW2h, sW2l, mrow0, nbase, lane, acc);

        int r0 = mrow0 + (lane >> 2);
#pragma unroll
        for (int j = 0; j < 8; j++) {
            int c = nbase + 8 * j + (lane & 3) * 2;
            float bx = __ldg(b2 + c), by = __ldg(b2 + c + 1);
            int gr0 = row0 + r0, gr1 = gr0 + 8;
            if (gr0 < nrows) {
                float2 o = make_float2(fmaxf(acc[j][0] + bx, 0.f),
                                       fmaxf(acc[j][1] + by, 0.f));
                *(float2*)(Out + (size_t)gr0 * HN + c) = o;
            }
            if (gr1 < nrows) {
                float2 o = make_float2(fmaxf(acc[j][2] + bx, 0.f),
                                       fmaxf(acc[j][3] + by, 0.f));
                *(float2*)(Out + (size_t)gr1 * HN + c) = o;
            }
        }
    }
}

// ---------------- pooling: direct nodes -> graphs (comp sorted) ----------------
__global__ void k_comp(const int* __restrict__ sub, const int* __restrict__ s2g,
                       int* __restrict__ comp, int n) {
    int i = blockIdx.x * blockDim.x + threadIdx.x;
    if (i < n) comp[i] = s2g[sub[i]];
}
__global__ void k_pool(const float* __restrict__ h, const int* __restrict__ comp,
                       float* __restrict__ out, int N) {
    int j = threadIdx.x;
    int per = (N + gridDim.x - 1) / gridDim.x;
    int n0 = blockIdx.x * per;
    int n1 = n0 + per; if (n1 > N) n1 = N;
    if (n0 >= n1) return;
    float acc = 0.f;
    int cur = __ldg(comp + n0);
    for (int i = n0; i < n1; i++) {
        int c = __ldg(comp + i);
        if (c != cur) {
            atomicAdd(out + (size_t)cur * HN + j, acc);
            acc = 0.f; cur = c;
        }
        acc += __ldg(h + (size_t)i * HN + j);
    }
    atomicAdd(out + (size_t)cur * HN + j, acc);
}

// ---------------- launch ----------------
extern "C" void kernel_launch(void* const* d_in, const int* in_sizes, int n_in,
                              void* d_out, int out_size) {
    const float* x     = (const float*)d_in[0];
    const void*  ei    = d_in[1];
    const void*  n2s   = d_in[2];
    const void*  s2g_i = d_in[3];
    const float* c1W1  = (const float*)d_in[4];
    const float* c1b1  = (const float*)d_in[5];
    const float* c1W2  = (const float*)d_in[6];
    const float* c1b2  = (const float*)d_in[7];
    const float* cW1   = (const float*)d_in[8];
    const float* cb1   = (const float*)d_in[9];
    const float* cW2   = (const float*)d_in[10];
    const float* cb2   = (const float*)d_in[11];

    int N = in_sizes[0];
    int E = in_sizes[1] / 2;
    int S = in_sizes[3];
    int G = out_size / HN;

    float *bufA, *bufB, *agg0;
    int *eiX, *sub, *s2gX, *comp, *deg, *offs, *cursor, *csr;
    __nv_bfloat16* ws;
    cudaGetSymbolAddress((void**)&bufA,   g_bufA);
    cudaGetSymbolAddress((void**)&bufB,   g_bufB);
    cudaGetSymbolAddress((void**)&agg0,   g_agg0);
    cudaGetSymbolAddress((void**)&eiX,    g_ei);
    cudaGetSymbolAddress((void**)&sub,    g_sub);
    cudaGetSymbolAddress((void**)&s2gX,   g_s2g);
    cudaGetSymbolAddress((void**)&comp,   g_comp);
    cudaGetSymbolAddress((void**)&deg,    g_deg);
    cudaGetSymbolAddress((void**)&offs,   g_offs);
    cudaGetSymbolAddress((void**)&cursor, g_cursor);
    cudaGetSymbolAddress((void**)&csr,    g_csr);
    cudaGetSymbolAddress((void**)&ws,     g_wsplit);

    const int SMEM = SMEM_ELEMS * 2;   // 208896 B
    cudaFuncSetAttribute(k_layer, cudaFuncAttributeMaxDynamicSharedMemorySize, SMEM);

    // normalize index dtypes
    k_detect<<<1, 1>>>((const unsigned long long*)ei);
    k_convert<<<(2 * E + 255) / 256, 256>>>(ei, eiX, 2 * E);
    k_convert<<<(N + 255) / 256, 256>>>(n2s, sub, N);
    k_convert<<<(S + 255) / 256, 256>>>(s2g_i, s2gX, S);
    k_comp<<<(N + 255) / 256, 256>>>(sub, s2gX, comp, N);

    // split the 5 [128,128] weight matrices into bf16 hi/lo planes
    // layout: m0 = c1W2, m1 = cW1[0], m2 = cW2[0], m3 = cW1[1], m4 = cW2[1]
    k_splitW<<<64, 256>>>(c1W2,             ws + 0 * 2 * PLANE, ws + 0 * 2 * PLANE + PLANE);
    k_splitW<<<64, 256>>>(cW1,              ws + 1 * 2 * PLANE, ws + 1 * 2 * PLANE + PLANE);
    k_splitW<<<64, 256>>>(cW2,              ws + 2 * 2 * PLANE, ws + 2 * 2 * PLANE + PLANE);
    k_splitW<<<64, 256>>>(cW1 + HN * HN,    ws + 3 * 2 * PLANE, ws + 3 * 2 * PLANE + PLANE);
    k_splitW<<<64, 256>>>(cW2 + HN * HN,    ws + 4 * 2 * PLANE, ws + 4 * 2 * PLANE + PLANE);

    // CSR build (dst-major)
    k_zeroi<<<(N + 255) / 256, 256>>>(deg, N);
    k_hist<<<(E + 255) / 256, 256>>>(eiX + E, deg, E);
    k_scan<<<1, 1024>>>(deg, offs, N);
    k_zeroi<<<(N + 255) / 256, 256>>>(cursor, N);
    k_scatter<<<(E + 255) / 256, 256>>>(eiX, eiX + E, offs, cursor, csr, E);

    int ablocks = (N * 32 + 255) / 256;
    const int LGRID = 148;

    // layer 1: scalar agg + fused (elementwise expansion, MMA phase2)
    k_agg0<<<ablocks, 256>>>(offs, csr, x, agg0, N);
    k_layer<<<LGRID, 256, SMEM>>>(nullptr, agg0, c1W1, nullptr, nullptr, c1b1,
                                  ws + 0 * 2 * PLANE, ws + 0 * 2 * PLANE + PLANE, c1b2,
                                  bufB, N, 0);

    // layers 2..3: CSR agg + fused dual MMA
    for (int i = 0; i < 2; i++) {
        k_agg_csr<<<ablocks, 256>>>(offs, csr, bufB, bufA, N);
        k_layer<<<LGRID, 256, SMEM>>>(bufA, nullptr, nullptr,
                                      ws + (1 + 2 * i) * 2 * PLANE,
                                      ws + (1 + 2 * i) * 2 * PLANE + PLANE,
                                      cb1 + (size_t)i * HN,
                                      ws + (2 + 2 * i) * 2 * PLANE,
                                      ws + (2 + 2 * i) * 2 * PLANE + PLANE,
                                      cb2 + (size_t)i * HN,
                                      bufB, N, 1);
    }

    // pooling: nodes -> graphs via composed index
    k_zero4<<<((G * HN / 4) + 255) / 256, 256>>>((float*)d_out, G * HN / 4);
    k_pool<<<512, HN>>>(bufB, comp, (float*)d_out, N);
}